// round 1
// baseline (speedup 1.0000x reference)
#include <cuda_runtime.h>

// Problem constants
#define C_DIM 256
#define NPIX  4096          // 64*64
#define BATCH 16

// Scratch (allocation-free rule: __device__ globals)
__device__ float g_phi_q[BATCH * C_DIM * NPIX];   // 64 MB
__device__ float g_phi_k[BATCH * C_DIM * NPIX];   // 64 MB
__device__ float g_phi_v[BATCH * C_DIM * NPIX];   // 64 MB
__device__ float g_qv  [BATCH * C_DIM * C_DIM];   // 4 MB
__device__ float g_m   [BATCH * C_DIM * C_DIM];   // 4 MB

__device__ __forceinline__ float phi_f(float x) {
    // elu(x)+1 : x>0 -> x+1 ; x<=0 -> exp(x)
    return x > 0.0f ? x + 1.0f : __expf(x);
}

// ---------------------------------------------------------------------------
// Kernel A: fused QKV projection + phi.
//   phi_{q,k,v}[b,o,n] = phi( sum_c W{q,k,v}[o,c] * x[b,c,n] )
// GEMM shape per batch: [256 x 256] @ [256 x 4096].
// Tile: BM=64, BN=64, BK=16, 256 threads, 4x4 micro-tile, 3 accumulator sets.
// ---------------------------------------------------------------------------
__global__ void __launch_bounds__(256)
qkv_phi_kernel(const float* __restrict__ x,
               const float* __restrict__ Wq,
               const float* __restrict__ Wk,
               const float* __restrict__ Wv)
{
    __shared__ __align__(16) float As[3][16][64];   // [w][k][m]
    __shared__ __align__(16) float Bs[16][64];      // [k][n]

    const int b  = blockIdx.z;
    const int m0 = blockIdx.y * 64;
    const int n0 = blockIdx.x * 64;
    const float* X = x + (size_t)b * C_DIM * NPIX;

    const int tid  = threadIdx.x;
    const int tx   = tid & 15;          // 0..15 (n)
    const int ty   = tid >> 4;          // 0..15 (m)
    const int arow = tid >> 2;          // 0..63  m within tile
    const int acol = (tid & 3) << 2;    // 0..12  k group
    const int brow = tid >> 4;          // 0..15  k
    const int bcol = (tid & 15) << 2;   // 0..60  n group

    float acc[3][4][4];
#pragma unroll
    for (int s = 0; s < 3; s++)
#pragma unroll
        for (int i = 0; i < 4; i++)
#pragma unroll
            for (int j = 0; j < 4; j++) acc[s][i][j] = 0.0f;

    for (int k0 = 0; k0 < C_DIM; k0 += 16) {
        const float4 aq = *(const float4*)(Wq + (size_t)(m0 + arow) * C_DIM + k0 + acol);
        const float4 ak = *(const float4*)(Wk + (size_t)(m0 + arow) * C_DIM + k0 + acol);
        const float4 av = *(const float4*)(Wv + (size_t)(m0 + arow) * C_DIM + k0 + acol);
        As[0][acol + 0][arow] = aq.x; As[0][acol + 1][arow] = aq.y;
        As[0][acol + 2][arow] = aq.z; As[0][acol + 3][arow] = aq.w;
        As[1][acol + 0][arow] = ak.x; As[1][acol + 1][arow] = ak.y;
        As[1][acol + 2][arow] = ak.z; As[1][acol + 3][arow] = ak.w;
        As[2][acol + 0][arow] = av.x; As[2][acol + 1][arow] = av.y;
        As[2][acol + 2][arow] = av.z; As[2][acol + 3][arow] = av.w;

        const float4 bx = *(const float4*)(X + (size_t)(k0 + brow) * NPIX + n0 + bcol);
        *(float4*)&Bs[brow][bcol] = bx;

        __syncthreads();
#pragma unroll
        for (int k = 0; k < 16; k++) {
            const float4 bb = *(const float4*)&Bs[k][tx << 2];
            const float4 q4 = *(const float4*)&As[0][k][ty << 2];
            const float4 k4 = *(const float4*)&As[1][k][ty << 2];
            const float4 v4 = *(const float4*)&As[2][k][ty << 2];
            const float bv[4] = {bb.x, bb.y, bb.z, bb.w};
            const float qa[4] = {q4.x, q4.y, q4.z, q4.w};
            const float ka[4] = {k4.x, k4.y, k4.z, k4.w};
            const float va[4] = {v4.x, v4.y, v4.z, v4.w};
#pragma unroll
            for (int i = 0; i < 4; i++)
#pragma unroll
                for (int j = 0; j < 4; j++) {
                    acc[0][i][j] += qa[i] * bv[j];
                    acc[1][i][j] += ka[i] * bv[j];
                    acc[2][i][j] += va[i] * bv[j];
                }
        }
        __syncthreads();
    }

    const size_t base = (size_t)b * C_DIM * NPIX;
#pragma unroll
    for (int i = 0; i < 4; i++) {
        const int row = m0 + (ty << 2) + i;
        const size_t off = base + (size_t)row * NPIX + n0 + (tx << 2);
        float4 oq, ok, ov;
        oq.x = phi_f(acc[0][i][0]); oq.y = phi_f(acc[0][i][1]);
        oq.z = phi_f(acc[0][i][2]); oq.w = phi_f(acc[0][i][3]);
        ok.x = phi_f(acc[1][i][0]); ok.y = phi_f(acc[1][i][1]);
        ok.z = phi_f(acc[1][i][2]); ok.w = phi_f(acc[1][i][3]);
        ov.x = phi_f(acc[2][i][0]); ov.y = phi_f(acc[2][i][1]);
        ov.z = phi_f(acc[2][i][2]); ov.w = phi_f(acc[2][i][3]);
        *(float4*)(g_phi_q + off) = oq;
        *(float4*)(g_phi_k + off) = ok;
        *(float4*)(g_phi_v + off) = ov;
    }
}

// ---------------------------------------------------------------------------
// Kernel B: qv[b] = phi_q[b] @ phi_v[b]^T      (NT GEMM, M=N=256, K=4096)
// qv[c,d] = sum_n phi_q[c,n] * phi_v[d,n]
// ---------------------------------------------------------------------------
__global__ void __launch_bounds__(256)
qv_kernel()
{
    __shared__ __align__(16) float As[16][64];   // [k][m]
    __shared__ __align__(16) float Bs[16][64];   // [k][n]

    const int b  = blockIdx.z;
    const int m0 = blockIdx.y * 64;
    const int n0 = blockIdx.x * 64;
    const float* A = g_phi_q + (size_t)b * C_DIM * NPIX;
    const float* B = g_phi_v + (size_t)b * C_DIM * NPIX;

    const int tid  = threadIdx.x;
    const int tx   = tid & 15;
    const int ty   = tid >> 4;
    const int arow = tid >> 2;          // 0..63
    const int acol = (tid & 3) << 2;    // 0..12

    float acc[4][4];
#pragma unroll
    for (int i = 0; i < 4; i++)
#pragma unroll
        for (int j = 0; j < 4; j++) acc[i][j] = 0.0f;

    for (int k0 = 0; k0 < NPIX; k0 += 16) {
        const float4 a4 = *(const float4*)(A + (size_t)(m0 + arow) * NPIX + k0 + acol);
        As[acol + 0][arow] = a4.x; As[acol + 1][arow] = a4.y;
        As[acol + 2][arow] = a4.z; As[acol + 3][arow] = a4.w;
        const float4 b4 = *(const float4*)(B + (size_t)(n0 + arow) * NPIX + k0 + acol);
        Bs[acol + 0][arow] = b4.x; Bs[acol + 1][arow] = b4.y;
        Bs[acol + 2][arow] = b4.z; Bs[acol + 3][arow] = b4.w;

        __syncthreads();
#pragma unroll
        for (int k = 0; k < 16; k++) {
            const float4 a = *(const float4*)&As[k][ty << 2];
            const float4 c = *(const float4*)&Bs[k][tx << 2];
            const float av[4] = {a.x, a.y, a.z, a.w};
            const float bv[4] = {c.x, c.y, c.z, c.w};
#pragma unroll
            for (int i = 0; i < 4; i++)
#pragma unroll
                for (int j = 0; j < 4; j++)
                    acc[i][j] += av[i] * bv[j];
        }
        __syncthreads();
    }

    float* Cb = g_qv + (size_t)b * C_DIM * C_DIM;
#pragma unroll
    for (int i = 0; i < 4; i++) {
        const int row = m0 + (ty << 2) + i;
        float4 o;
        o.x = acc[i][0]; o.y = acc[i][1]; o.z = acc[i][2]; o.w = acc[i][3];
        *(float4*)(Cb + (size_t)row * C_DIM + n0 + (tx << 2)) = o;
    }
}

// ---------------------------------------------------------------------------
// Kernel C: g_m[b] = Wo @ g_qv[b]              (NN GEMM, M=N=K=256)
// ---------------------------------------------------------------------------
__global__ void __launch_bounds__(256)
wo_qv_kernel(const float* __restrict__ Wo)
{
    __shared__ __align__(16) float As[16][64];   // [k][m]
    __shared__ __align__(16) float Bs[16][64];   // [k][n]

    const int b  = blockIdx.z;
    const int m0 = blockIdx.y * 64;
    const int n0 = blockIdx.x * 64;
    const float* B = g_qv + (size_t)b * C_DIM * C_DIM;

    const int tid  = threadIdx.x;
    const int tx   = tid & 15;
    const int ty   = tid >> 4;
    const int arow = tid >> 2;
    const int acol = (tid & 3) << 2;
    const int brow = tid >> 4;
    const int bcol = (tid & 15) << 2;

    float acc[4][4];
#pragma unroll
    for (int i = 0; i < 4; i++)
#pragma unroll
        for (int j = 0; j < 4; j++) acc[i][j] = 0.0f;

    for (int k0 = 0; k0 < C_DIM; k0 += 16) {
        const float4 a4 = *(const float4*)(Wo + (size_t)(m0 + arow) * C_DIM + k0 + acol);
        As[acol + 0][arow] = a4.x; As[acol + 1][arow] = a4.y;
        As[acol + 2][arow] = a4.z; As[acol + 3][arow] = a4.w;
        const float4 b4 = *(const float4*)(B + (size_t)(k0 + brow) * C_DIM + n0 + bcol);
        *(float4*)&Bs[brow][bcol] = b4;

        __syncthreads();
#pragma unroll
        for (int k = 0; k < 16; k++) {
            const float4 a = *(const float4*)&As[k][ty << 2];
            const float4 c = *(const float4*)&Bs[k][tx << 2];
            const float av[4] = {a.x, a.y, a.z, a.w};
            const float bv[4] = {c.x, c.y, c.z, c.w};
#pragma unroll
            for (int i = 0; i < 4; i++)
#pragma unroll
                for (int j = 0; j < 4; j++)
                    acc[i][j] += av[i] * bv[j];
        }
        __syncthreads();
    }

    float* Cb = g_m + (size_t)b * C_DIM * C_DIM;
#pragma unroll
    for (int i = 0; i < 4; i++) {
        const int row = m0 + (ty << 2) + i;
        float4 o;
        o.x = acc[i][0]; o.y = acc[i][1]; o.z = acc[i][2]; o.w = acc[i][3];
        *(float4*)(Cb + (size_t)row * C_DIM + n0 + (tx << 2)) = o;
    }
}

// ---------------------------------------------------------------------------
// Kernel D: out[b] = g_m[b] @ phi_k[b] + bo    (NN GEMM, M=256, N=4096, K=256)
// ---------------------------------------------------------------------------
__global__ void __launch_bounds__(256)
out_kernel(const float* __restrict__ bo, float* __restrict__ out)
{
    __shared__ __align__(16) float As[16][64];   // [k][m]
    __shared__ __align__(16) float Bs[16][64];   // [k][n]

    const int b  = blockIdx.z;
    const int m0 = blockIdx.y * 64;
    const int n0 = blockIdx.x * 64;
    const float* A = g_m     + (size_t)b * C_DIM * C_DIM;
    const float* B = g_phi_k + (size_t)b * C_DIM * NPIX;

    const int tid  = threadIdx.x;
    const int tx   = tid & 15;
    const int ty   = tid >> 4;
    const int arow = tid >> 2;
    const int acol = (tid & 3) << 2;
    const int brow = tid >> 4;
    const int bcol = (tid & 15) << 2;

    float acc[4][4];
#pragma unroll
    for (int i = 0; i < 4; i++)
#pragma unroll
        for (int j = 0; j < 4; j++) acc[i][j] = 0.0f;

    for (int k0 = 0; k0 < C_DIM; k0 += 16) {
        const float4 a4 = *(const float4*)(A + (size_t)(m0 + arow) * C_DIM + k0 + acol);
        As[acol + 0][arow] = a4.x; As[acol + 1][arow] = a4.y;
        As[acol + 2][arow] = a4.z; As[acol + 3][arow] = a4.w;
        const float4 b4 = *(const float4*)(B + (size_t)(k0 + brow) * NPIX + n0 + bcol);
        *(float4*)&Bs[brow][bcol] = b4;

        __syncthreads();
#pragma unroll
        for (int k = 0; k < 16; k++) {
            const float4 a = *(const float4*)&As[k][ty << 2];
            const float4 c = *(const float4*)&Bs[k][tx << 2];
            const float av[4] = {a.x, a.y, a.z, a.w};
            const float bv[4] = {c.x, c.y, c.z, c.w};
#pragma unroll
            for (int i = 0; i < 4; i++)
#pragma unroll
                for (int j = 0; j < 4; j++)
                    acc[i][j] += av[i] * bv[j];
        }
        __syncthreads();
    }

    float* Ob = out + (size_t)b * C_DIM * NPIX;
#pragma unroll
    for (int i = 0; i < 4; i++) {
        const int row  = m0 + (ty << 2) + i;
        const float bi = bo[row];
        float4 o;
        o.x = acc[i][0] + bi; o.y = acc[i][1] + bi;
        o.z = acc[i][2] + bi; o.w = acc[i][3] + bi;
        *(float4*)(Ob + (size_t)row * NPIX + n0 + (tx << 2)) = o;
    }
}

// ---------------------------------------------------------------------------
// Launch
// ---------------------------------------------------------------------------
extern "C" void kernel_launch(void* const* d_in, const int* in_sizes, int n_in,
                              void* d_out, int out_size)
{
    const float* x  = (const float*)d_in[0];
    const float* Wq = (const float*)d_in[1];
    const float* Wk = (const float*)d_in[2];
    const float* Wv = (const float*)d_in[3];
    const float* Wo = (const float*)d_in[4];
    const float* bo = (const float*)d_in[5];
    float* out = (float*)d_out;

    // A: phi(QKV) — grid (N/64, M/64, B) = (64, 4, 16)
    qkv_phi_kernel<<<dim3(NPIX / 64, C_DIM / 64, BATCH), 256>>>(x, Wq, Wk, Wv);

    // B: qv = phi_q @ phi_v^T — grid (4, 4, 16)
    qv_kernel<<<dim3(C_DIM / 64, C_DIM / 64, BATCH), 256>>>();

    // C: m = Wo @ qv — grid (4, 4, 16)
    wo_qv_kernel<<<dim3(C_DIM / 64, C_DIM / 64, BATCH), 256>>>(Wo);

    // D: out = m @ phi_k + bo — grid (64, 4, 16)
    out_kernel<<<dim3(NPIX / 64, C_DIM / 64, BATCH), 256>>>(bo, out);
}

// round 3
// speedup vs baseline: 1.6089x; 1.6089x over previous
#include <cuda_runtime.h>
#include <cstdint>

#define C_DIM 256
#define NPIX  4096
#define BATCH 16

// Scratch (allocation-free rule: __device__ globals)
__device__ float g_Wqkv [3 * C_DIM * C_DIM];       // packed [768][256]
__device__ float g_phi_q[BATCH * C_DIM * NPIX];    // 64 MB
__device__ float g_phi_k[BATCH * C_DIM * NPIX];    // 64 MB
__device__ float g_phi_v[BATCH * C_DIM * NPIX];    // 64 MB
__device__ float g_qv   [BATCH * C_DIM * C_DIM];   // 4 MB
__device__ float g_m    [BATCH * C_DIM * C_DIM];   // 4 MB

__device__ __forceinline__ float phi_f(float x) {
    return x > 0.0f ? x + 1.0f : __expf(x);
}

__device__ __forceinline__ uint32_t f2tf32(float f) {
    uint32_t r;
    asm("cvt.rna.tf32.f32 %0, %1;" : "=r"(r) : "f"(f));
    return r;
}

__device__ __forceinline__ void mma_tf32(float c[4], const uint32_t a[4],
                                         uint32_t b0, uint32_t b1) {
    asm volatile(
        "mma.sync.aligned.m16n8k8.row.col.f32.tf32.tf32.f32 "
        "{%0,%1,%2,%3},{%4,%5,%6,%7},{%8,%9},{%0,%1,%2,%3};"
        : "+f"(c[0]), "+f"(c[1]), "+f"(c[2]), "+f"(c[3])
        : "r"(a[0]), "r"(a[1]), "r"(a[2]), "r"(a[3]), "r"(b0), "r"(b1));
}

// Tile geometry: BM=128, BN=128, BK=32, 256 threads = 8 warps (4m x 2n),
// warp tile 32x64 -> 2 m-subtiles x 8 n-subtiles of m16n8k8.
#define LDA_S 36          // 32 + 4 pad (row-major [rows][32] tiles)
#define LDB_S 136         // 128 + 8 pad (NN B tile [32][128])
#define SMEM_A_WORDS (128 * LDA_S)   // 4608
#define SMEM_B_WORDS (128 * LDA_S)   // max(128*36, 32*136) = 4608

// Core mainloop. BT=false: B global is [K][N] (pass B pre-offset by n0 cols).
//                BT=true : B global is [N][K] (pass B pre-offset by n0 rows).
template<bool BT>
__device__ __forceinline__ void gemm_core(const float* __restrict__ A,
                                          const float* __restrict__ B,
                                          int K, int lda, int ldb,
                                          float c[2][8][4], uint32_t* smem)
{
    uint32_t* As = smem;
    uint32_t* Bs = smem + SMEM_A_WORDS;

    const int tid  = threadIdx.x;
    const int lane = tid & 31;
    const int wid  = tid >> 5;
    const int g    = lane >> 2;   // 0..7
    const int t    = lane & 3;    // 0..3
    const int wm   = (wid & 3) * 32;
    const int wn   = (wid >> 2) * 64;

    for (int k0 = 0; k0 < K; k0 += 32) {
        // ---- load A tile: 128 rows x 32 cols, 4 float4 per thread ----
#pragma unroll
        for (int p = 0; p < 4; p++) {
            const int idx = tid + p * 256;
            const int r  = idx >> 3;
            const int c4 = (idx & 7) << 2;
            const float4 v = *(const float4*)(A + (size_t)r * lda + k0 + c4);
            uint4 u;
            u.x = f2tf32(v.x); u.y = f2tf32(v.y);
            u.z = f2tf32(v.z); u.w = f2tf32(v.w);
            *(uint4*)&As[r * LDA_S + c4] = u;
        }
        // ---- load B tile ----
        if (BT) {
            // [128 n-rows][32 k] from B[N][K]
#pragma unroll
            for (int p = 0; p < 4; p++) {
                const int idx = tid + p * 256;
                const int r  = idx >> 3;
                const int c4 = (idx & 7) << 2;
                const float4 v = *(const float4*)(B + (size_t)r * ldb + k0 + c4);
                uint4 u;
                u.x = f2tf32(v.x); u.y = f2tf32(v.y);
                u.z = f2tf32(v.z); u.w = f2tf32(v.w);
                *(uint4*)&Bs[r * LDA_S + c4] = u;
            }
        } else {
            // [32 k][128 n] from B[K][N]
#pragma unroll
            for (int p = 0; p < 4; p++) {
                const int idx = tid + p * 256;
                const int r  = idx >> 5;
                const int c4 = (idx & 31) << 2;
                const float4 v = *(const float4*)(B + (size_t)(k0 + r) * ldb + c4);
                uint4 u;
                u.x = f2tf32(v.x); u.y = f2tf32(v.y);
                u.z = f2tf32(v.z); u.w = f2tf32(v.w);
                *(uint4*)&Bs[r * LDB_S + c4] = u;
            }
        }
        __syncthreads();

        // ---- compute: 4 k-substeps of 8 ----
#pragma unroll
        for (int ks = 0; ks < 32; ks += 8) {
            uint32_t a[2][4];
#pragma unroll
            for (int mi = 0; mi < 2; mi++) {
                const int base = wm + mi * 16 + g;
                a[mi][0] = As[(base    ) * LDA_S + ks + t    ];
                a[mi][1] = As[(base + 8) * LDA_S + ks + t    ];
                a[mi][2] = As[(base    ) * LDA_S + ks + t + 4];
                a[mi][3] = As[(base + 8) * LDA_S + ks + t + 4];
            }
#pragma unroll
            for (int ni = 0; ni < 8; ni++) {
                const int col = wn + ni * 8 + g;
                uint32_t b0, b1;
                if (BT) {
                    b0 = Bs[col * LDA_S + ks + t    ];
                    b1 = Bs[col * LDA_S + ks + t + 4];
                } else {
                    b0 = Bs[(ks + t    ) * LDB_S + col];
                    b1 = Bs[(ks + t + 4) * LDB_S + col];
                }
                mma_tf32(c[0][ni], a[0], b0, b1);
                mma_tf32(c[1][ni], a[1], b0, b1);
            }
        }
        __syncthreads();
    }
}

// ---------------------------------------------------------------------------
// Pack Wq,Wk,Wv -> g_Wqkv [768][256]
// ---------------------------------------------------------------------------
__global__ void pack_w(const float* __restrict__ q, const float* __restrict__ k,
                       const float* __restrict__ v)
{
    const int i = blockIdx.x * 256 + threadIdx.x;
    g_Wqkv[i]                       = q[i];
    g_Wqkv[C_DIM * C_DIM + i]       = k[i];
    g_Wqkv[2 * C_DIM * C_DIM + i]   = v[i];
}

// ---------------------------------------------------------------------------
// Kernel A: [768x256] @ x[b][256x4096] -> phi -> {g_phi_q, g_phi_k, g_phi_v}
// ---------------------------------------------------------------------------
__global__ void __launch_bounds__(256)
qkv_kernel(const float* __restrict__ x)
{
    __shared__ uint32_t smem[SMEM_A_WORDS + SMEM_B_WORDS];

    const int b  = blockIdx.z;
    const int m0 = blockIdx.y * 128;          // 0..640, within one weight group
    const int n0 = blockIdx.x * 128;

    const float* A = g_Wqkv + (size_t)m0 * C_DIM;
    const float* B = x + (size_t)b * C_DIM * NPIX + n0;

    float c[2][8][4];
#pragma unroll
    for (int mi = 0; mi < 2; mi++)
#pragma unroll
        for (int ni = 0; ni < 8; ni++)
#pragma unroll
            for (int e = 0; e < 4; e++) c[mi][ni][e] = 0.0f;

    gemm_core<false>(A, B, C_DIM, C_DIM, NPIX, c, smem);

    // which output buffer: rows m0..m0+127 all in one 256-row group
    float* bufs[3] = {g_phi_q, g_phi_k, g_phi_v};
    float* Ob = bufs[m0 >> 8] + (size_t)b * C_DIM * NPIX;
    const int rowc0 = m0 & 255;

    const int lane = threadIdx.x & 31;
    const int wid  = threadIdx.x >> 5;
    const int g    = lane >> 2;
    const int t    = lane & 3;
    const int wm   = (wid & 3) * 32;
    const int wn   = (wid >> 2) * 64;

#pragma unroll
    for (int mi = 0; mi < 2; mi++)
#pragma unroll
        for (int ni = 0; ni < 8; ni++) {
            const int col = n0 + wn + ni * 8 + 2 * t;
#pragma unroll
            for (int h = 0; h < 2; h++) {     // h=0: rows g ; h=1: rows g+8
                const int row = rowc0 + wm + mi * 16 + g + h * 8;
                float2 o;
                o.x = phi_f(c[mi][ni][2 * h + 0]);
                o.y = phi_f(c[mi][ni][2 * h + 1]);
                *(float2*)(Ob + (size_t)row * NPIX + col) = o;
            }
        }
}

// ---------------------------------------------------------------------------
// Kernel B: qv[b] = phi_q[b] @ phi_v[b]^T   (NT, M=N=256, K=4096)
// ---------------------------------------------------------------------------
__global__ void __launch_bounds__(256)
qv_kernel()
{
    __shared__ uint32_t smem[SMEM_A_WORDS + SMEM_B_WORDS];

    const int b  = blockIdx.z;
    const int m0 = blockIdx.y * 128;
    const int n0 = blockIdx.x * 128;

    const float* A = g_phi_q + (size_t)b * C_DIM * NPIX + (size_t)m0 * NPIX;
    const float* B = g_phi_v + (size_t)b * C_DIM * NPIX + (size_t)n0 * NPIX;

    float c[2][8][4];
#pragma unroll
    for (int mi = 0; mi < 2; mi++)
#pragma unroll
        for (int ni = 0; ni < 8; ni++)
#pragma unroll
            for (int e = 0; e < 4; e++) c[mi][ni][e] = 0.0f;

    gemm_core<true>(A, B, NPIX, NPIX, NPIX, c, smem);

    float* Cb = g_qv + (size_t)b * C_DIM * C_DIM;

    const int lane = threadIdx.x & 31;
    const int wid  = threadIdx.x >> 5;
    const int g    = lane >> 2;
    const int t    = lane & 3;
    const int wm   = (wid & 3) * 32;
    const int wn   = (wid >> 2) * 64;

#pragma unroll
    for (int mi = 0; mi < 2; mi++)
#pragma unroll
        for (int ni = 0; ni < 8; ni++) {
            const int col = n0 + wn + ni * 8 + 2 * t;
#pragma unroll
            for (int h = 0; h < 2; h++) {
                const int row = m0 + wm + mi * 16 + g + h * 8;
                float2 o;
                o.x = c[mi][ni][2 * h + 0];
                o.y = c[mi][ni][2 * h + 1];
                *(float2*)(Cb + (size_t)row * C_DIM + col) = o;
            }
        }
}

// ---------------------------------------------------------------------------
// Kernel C: m[b] = Wo @ qv[b]   (NN, M=N=K=256)
// ---------------------------------------------------------------------------
__global__ void __launch_bounds__(256)
wo_qv_kernel(const float* __restrict__ Wo)
{
    __shared__ uint32_t smem[SMEM_A_WORDS + SMEM_B_WORDS];

    const int b  = blockIdx.z;
    const int m0 = blockIdx.y * 128;
    const int n0 = blockIdx.x * 128;

    const float* A = Wo + (size_t)m0 * C_DIM;
    const float* B = g_qv + (size_t)b * C_DIM * C_DIM + n0;

    float c[2][8][4];
#pragma unroll
    for (int mi = 0; mi < 2; mi++)
#pragma unroll
        for (int ni = 0; ni < 8; ni++)
#pragma unroll
            for (int e = 0; e < 4; e++) c[mi][ni][e] = 0.0f;

    gemm_core<false>(A, B, C_DIM, C_DIM, C_DIM, c, smem);

    float* Cb = g_m + (size_t)b * C_DIM * C_DIM;

    const int lane = threadIdx.x & 31;
    const int wid  = threadIdx.x >> 5;
    const int g    = lane >> 2;
    const int t    = lane & 3;
    const int wm   = (wid & 3) * 32;
    const int wn   = (wid >> 2) * 64;

#pragma unroll
    for (int mi = 0; mi < 2; mi++)
#pragma unroll
        for (int ni = 0; ni < 8; ni++) {
            const int col = n0 + wn + ni * 8 + 2 * t;
#pragma unroll
            for (int h = 0; h < 2; h++) {
                const int row = m0 + wm + mi * 16 + g + h * 8;
                float2 o;
                o.x = c[mi][ni][2 * h + 0];
                o.y = c[mi][ni][2 * h + 1];
                *(float2*)(Cb + (size_t)row * C_DIM + col) = o;
            }
        }
}

// ---------------------------------------------------------------------------
// Kernel D: out[b] = m[b] @ phi_k[b] + bo   (NN, M=256, N=4096, K=256)
// ---------------------------------------------------------------------------
__global__ void __launch_bounds__(256)
out_kernel(const float* __restrict__ bo, float* __restrict__ out)
{
    __shared__ uint32_t smem[SMEM_A_WORDS + SMEM_B_WORDS];

    const int b  = blockIdx.z;
    const int m0 = blockIdx.y * 128;
    const int n0 = blockIdx.x * 128;

    const float* A = g_m + (size_t)b * C_DIM * C_DIM + (size_t)m0 * C_DIM;
    const float* B = g_phi_k + (size_t)b * C_DIM * NPIX + n0;

    float c[2][8][4];
#pragma unroll
    for (int mi = 0; mi < 2; mi++)
#pragma unroll
        for (int ni = 0; ni < 8; ni++)
#pragma unroll
            for (int e = 0; e < 4; e++) c[mi][ni][e] = 0.0f;

    gemm_core<false>(A, B, C_DIM, C_DIM, NPIX, c, smem);

    float* Ob = out + (size_t)b * C_DIM * NPIX;

    const int lane = threadIdx.x & 31;
    const int wid  = threadIdx.x >> 5;
    const int g    = lane >> 2;
    const int t    = lane & 3;
    const int wm   = (wid & 3) * 32;
    const int wn   = (wid >> 2) * 64;

#pragma unroll
    for (int mi = 0; mi < 2; mi++)
#pragma unroll
        for (int ni = 0; ni < 8; ni++) {
            const int col = n0 + wn + ni * 8 + 2 * t;
#pragma unroll
            for (int h = 0; h < 2; h++) {
                const int row = m0 + wm + mi * 16 + g + h * 8;
                const float bi = bo[row];
                float2 o;
                o.x = c[mi][ni][2 * h + 0] + bi;
                o.y = c[mi][ni][2 * h + 1] + bi;
                *(float2*)(Ob + (size_t)row * NPIX + col) = o;
            }
        }
}

// ---------------------------------------------------------------------------
// Launch
// ---------------------------------------------------------------------------
extern "C" void kernel_launch(void* const* d_in, const int* in_sizes, int n_in,
                              void* d_out, int out_size)
{
    const float* x  = (const float*)d_in[0];
    const float* Wq = (const float*)d_in[1];
    const float* Wk = (const float*)d_in[2];
    const float* Wv = (const float*)d_in[3];
    const float* Wo = (const float*)d_in[4];
    const float* bo = (const float*)d_in[5];
    float* out = (float*)d_out;

    pack_w<<<C_DIM * C_DIM / 256, 256>>>(Wq, Wk, Wv);

    // A: QKV + phi — grid (32, 6, 16)
    qkv_kernel<<<dim3(NPIX / 128, 3 * C_DIM / 128, BATCH), 256>>>(x);

    // B: qv = phi_q @ phi_v^T — grid (2, 2, 16)
    qv_kernel<<<dim3(C_DIM / 128, C_DIM / 128, BATCH), 256>>>();

    // C: m = Wo @ qv — grid (2, 2, 16)
    wo_qv_kernel<<<dim3(C_DIM / 128, C_DIM / 128, BATCH), 256>>>(Wo);

    // D: out = m @ phi_k + bo — grid (32, 2, 16)
    out_kernel<<<dim3(NPIX / 128, C_DIM / 128, BATCH), 256>>>(bo, out);
}

// round 6
// speedup vs baseline: 3.3515x; 2.0831x over previous
#include <cuda_runtime.h>
#include <cstdint>

#define C_DIM  256
#define NPIX   4096
#define BATCH  16
#define SPLITK 8

// ---------------------------------------------------------------------------
// Scratch (__device__ globals; allocation-free rule)
// ---------------------------------------------------------------------------
__device__ float g_Wqkv [3 * C_DIM * C_DIM];        // tf32 bits, packed [768][256]
__device__ float g_Wo   [C_DIM * C_DIM];            // tf32 bits
__device__ float g_x    [BATCH * C_DIM * NPIX];     // tf32 bits, 64 MB
__device__ float g_phi_q[BATCH * C_DIM * NPIX];     // tf32 bits
__device__ float g_phi_k[BATCH * C_DIM * NPIX];     // tf32 bits
__device__ float g_phi_v[BATCH * C_DIM * NPIX];     // tf32 bits
__device__ float g_qvp  [SPLITK * BATCH * C_DIM * C_DIM]; // fp32 partials
__device__ float g_qv   [BATCH * C_DIM * C_DIM];    // tf32 bits
__device__ float g_m    [BATCH * C_DIM * C_DIM];    // tf32 bits

__device__ __forceinline__ float phi_f(float x) {
    return x > 0.0f ? x + 1.0f : __expf(x);
}

__device__ __forceinline__ uint32_t f2tf32(float f) {
    uint32_t r;
    asm("cvt.rna.tf32.f32 %0, %1;" : "=r"(r) : "f"(f));
    return r;
}
__device__ __forceinline__ float f2tf32f(float f) {
    return __uint_as_float(f2tf32(f));
}

__device__ __forceinline__ void mma_tf32(float c[4], const uint32_t a[4],
                                         uint32_t b0, uint32_t b1) {
    asm volatile(
        "mma.sync.aligned.m16n8k8.row.col.f32.tf32.tf32.f32 "
        "{%0,%1,%2,%3},{%4,%5,%6,%7},{%8,%9},{%0,%1,%2,%3};"
        : "+f"(c[0]), "+f"(c[1]), "+f"(c[2]), "+f"(c[3])
        : "r"(a[0]), "r"(a[1]), "r"(a[2]), "r"(a[3]), "r"(b0), "r"(b1));
}

__device__ __forceinline__ void cpa16(uint32_t saddr, const void* gptr) {
    asm volatile("cp.async.cg.shared.global [%0], [%1], 16;"
                 :: "r"(saddr), "l"(gptr));
}
__device__ __forceinline__ void cpa_commit() {
    asm volatile("cp.async.commit_group;");
}
template<int N>
__device__ __forceinline__ void cpa_wait() {
    asm volatile("cp.async.wait_group %0;" :: "n"(N));
}

// ---------------------------------------------------------------------------
// GEMM core: BM=128, BN=128, BK=16, 256 threads = 8 warps (4m x 2n),
// warp tile 32x64, double-buffered cp.async, STATIC 40KB shared (no
// cudaFuncSetAttribute needed). Operands hold tf32 bit patterns.
// BT=false: B is [K][N] (pre-offset by n0 cols).
// BT=true : B is [N][K] (pre-offset by n0 rows).
// ---------------------------------------------------------------------------
#define LDA_S 20                          // 16 + 4 pad (80B rows: 16B aligned)
#define LDB_S 136                         // 128 + 8 pad (NN B tile [16][128])
#define A_WORDS (128 * LDA_S)             // 2560
#define B_WORDS (128 * LDA_S)             // 2560 (NN uses 16*136=2176 of it)
#define STAGE_WORDS (A_WORDS + B_WORDS)   // 5120
#define SMEM_WORDS (2 * STAGE_WORDS)      // 10240 words = 40 KB

template<bool BT>
__device__ __forceinline__ void gemm_core(const float* __restrict__ A,
                                          const float* __restrict__ B,
                                          int K, int lda, int ldb,
                                          float c[2][8][4], uint32_t* smem_w)
{
    const uint32_t smem_u = (uint32_t)__cvta_generic_to_shared(smem_w);

    const int tid  = threadIdx.x;
    const int lane = tid & 31;
    const int wid  = tid >> 5;
    const int g    = lane >> 2;
    const int t    = lane & 3;
    const int wm   = (wid & 3) * 32;
    const int wn   = (wid >> 2) * 64;

    // per-thread load coordinates (per 128x16 tile: 512 float4, 2/thread)
    const int ar  = tid >> 2;             // 0..63 (stride 64 over p)
    const int ac4 = (tid & 3) << 2;       // 0,4,8,12
    const int br  = tid >> 5;             // NN: 0..7 (stride 8 over p)
    const int bc4 = (tid & 31) << 2;      // 0..124

    const int niter = K >> 4;

    auto load_stage = [&](int s, int k0) {
        const uint32_t sa = smem_u + (uint32_t)(s * STAGE_WORDS) * 4;
        const uint32_t sb = sa + A_WORDS * 4;
#pragma unroll
        for (int p = 0; p < 2; p++) {
            const int r = ar + p * 64;
            cpa16(sa + (uint32_t)(r * LDA_S + ac4) * 4,
                  A + (size_t)r * lda + k0 + ac4);
        }
        if (BT) {
#pragma unroll
            for (int p = 0; p < 2; p++) {
                const int r = ar + p * 64;
                cpa16(sb + (uint32_t)(r * LDA_S + ac4) * 4,
                      B + (size_t)r * ldb + k0 + ac4);
            }
        } else {
#pragma unroll
            for (int p = 0; p < 2; p++) {
                const int r = br + p * 8;
                cpa16(sb + (uint32_t)(r * LDB_S + bc4) * 4,
                      B + (size_t)(k0 + r) * ldb + bc4);
            }
        }
        cpa_commit();
    };

    load_stage(0, 0);

    for (int it = 0; it < niter; it++) {
        if (it + 1 < niter) {
            load_stage((it + 1) & 1, (it + 1) << 4);
            cpa_wait<1>();
        } else {
            cpa_wait<0>();
        }
        __syncthreads();

        uint32_t* As = smem_w + (it & 1) * STAGE_WORDS;
        uint32_t* Bs = As + A_WORDS;

#pragma unroll
        for (int ks = 0; ks < 16; ks += 8) {
            uint32_t a[2][4];
#pragma unroll
            for (int mi = 0; mi < 2; mi++) {
                const int base = wm + mi * 16 + g;
                a[mi][0] = As[(base    ) * LDA_S + ks + t    ];
                a[mi][1] = As[(base + 8) * LDA_S + ks + t    ];
                a[mi][2] = As[(base    ) * LDA_S + ks + t + 4];
                a[mi][3] = As[(base + 8) * LDA_S + ks + t + 4];
            }
#pragma unroll
            for (int ni = 0; ni < 8; ni++) {
                const int col = wn + ni * 8 + g;
                uint32_t b0, b1;
                if (BT) {
                    b0 = Bs[col * LDA_S + ks + t    ];
                    b1 = Bs[col * LDA_S + ks + t + 4];
                } else {
                    b0 = Bs[(ks + t    ) * LDB_S + col];
                    b1 = Bs[(ks + t + 4) * LDB_S + col];
                }
                mma_tf32(c[0][ni], a[0], b0, b1);
                mma_tf32(c[1][ni], a[1], b0, b1);
            }
        }
        __syncthreads();
    }
}

#define ACC_INIT(c)                                   \
    _Pragma("unroll")                                 \
    for (int mi = 0; mi < 2; mi++)                    \
        _Pragma("unroll")                             \
        for (int ni = 0; ni < 8; ni++)                \
            _Pragma("unroll")                         \
            for (int e = 0; e < 4; e++) c[mi][ni][e] = 0.0f;

// ---------------------------------------------------------------------------
// Prep kernels
// ---------------------------------------------------------------------------
__global__ void pack_w(const float* __restrict__ q, const float* __restrict__ k,
                       const float* __restrict__ v, const float* __restrict__ o)
{
    const int i = blockIdx.x * 256 + threadIdx.x;
    g_Wqkv[i]                     = f2tf32f(q[i]);
    g_Wqkv[C_DIM * C_DIM + i]     = f2tf32f(k[i]);
    g_Wqkv[2 * C_DIM * C_DIM + i] = f2tf32f(v[i]);
    g_Wo[i]                       = f2tf32f(o[i]);
}

__global__ void cvt_x_kernel(const float* __restrict__ x)
{
    const size_t i = ((size_t)blockIdx.x * 256 + threadIdx.x) * 4;
    const float4 v = *(const float4*)(x + i);
    float4 u;
    u.x = f2tf32f(v.x); u.y = f2tf32f(v.y);
    u.z = f2tf32f(v.z); u.w = f2tf32f(v.w);
    *(float4*)(g_x + i) = u;
}

// ---------------------------------------------------------------------------
// A: [768x256] @ x_tf32[b][256x4096] -> phi -> tf32 -> g_phi_{q,k,v}
// ---------------------------------------------------------------------------
__global__ void __launch_bounds__(256, 2)
qkv_kernel()
{
    __shared__ uint32_t smem[SMEM_WORDS];
    const int b  = blockIdx.z;
    const int m0 = blockIdx.y * 128;
    const int n0 = blockIdx.x * 128;

    const float* A = g_Wqkv + (size_t)m0 * C_DIM;
    const float* B = g_x + (size_t)b * C_DIM * NPIX + n0;

    float c[2][8][4];
    ACC_INIT(c)
    gemm_core<false>(A, B, C_DIM, C_DIM, NPIX, c, smem);

    float* bufs[3] = {g_phi_q, g_phi_k, g_phi_v};
    float* Ob = bufs[m0 >> 8] + (size_t)b * C_DIM * NPIX;
    const int rowc0 = m0 & 255;

    const int lane = threadIdx.x & 31;
    const int wid  = threadIdx.x >> 5;
    const int g    = lane >> 2;
    const int t    = lane & 3;
    const int wm   = (wid & 3) * 32;
    const int wn   = (wid >> 2) * 64;

#pragma unroll
    for (int mi = 0; mi < 2; mi++)
#pragma unroll
        for (int ni = 0; ni < 8; ni++) {
            const int col = n0 + wn + ni * 8 + 2 * t;
#pragma unroll
            for (int h = 0; h < 2; h++) {
                const int row = rowc0 + wm + mi * 16 + g + h * 8;
                float2 o;
                o.x = f2tf32f(phi_f(c[mi][ni][2 * h + 0]));
                o.y = f2tf32f(phi_f(c[mi][ni][2 * h + 1]));
                *(float2*)(Ob + (size_t)row * NPIX + col) = o;
            }
        }
}

// ---------------------------------------------------------------------------
// B: split-K qv partials: g_qvp[b*8+sp] = phi_q[b][:, sp*512:+512] @ phi_v^T
// ---------------------------------------------------------------------------
__global__ void __launch_bounds__(256, 2)
qv_kernel()
{
    __shared__ uint32_t smem[SMEM_WORDS];
    const int z  = blockIdx.z;
    const int b  = z >> 3;
    const int sp = z & 7;
    const int m0 = blockIdx.y * 128;
    const int n0 = blockIdx.x * 128;
    const int kofs = sp * (NPIX / SPLITK);

    const float* A = g_phi_q + (size_t)b * C_DIM * NPIX + (size_t)m0 * NPIX + kofs;
    const float* B = g_phi_v + (size_t)b * C_DIM * NPIX + (size_t)n0 * NPIX + kofs;

    float c[2][8][4];
    ACC_INIT(c)
    gemm_core<true>(A, B, NPIX / SPLITK, NPIX, NPIX, c, smem);

    float* Cb = g_qvp + (size_t)z * C_DIM * C_DIM;

    const int lane = threadIdx.x & 31;
    const int wid  = threadIdx.x >> 5;
    const int g    = lane >> 2;
    const int t    = lane & 3;
    const int wm   = (wid & 3) * 32;
    const int wn   = (wid >> 2) * 64;

#pragma unroll
    for (int mi = 0; mi < 2; mi++)
#pragma unroll
        for (int ni = 0; ni < 8; ni++) {
            const int col = n0 + wn + ni * 8 + 2 * t;
#pragma unroll
            for (int h = 0; h < 2; h++) {
                const int row = m0 + wm + mi * 16 + g + h * 8;
                float2 o;
                o.x = c[mi][ni][2 * h + 0];
                o.y = c[mi][ni][2 * h + 1];
                *(float2*)(Cb + (size_t)row * C_DIM + col) = o;
            }
        }
}

// Deterministic fixed-order reduction + tf32 convert
__global__ void qv_reduce()
{
    const int j = blockIdx.x * 256 + threadIdx.x;    // 0 .. 16*65536-1
    const int b = j >> 16;
    const int i = j & 65535;
    const float* p = g_qvp + (size_t)b * SPLITK * C_DIM * C_DIM + i;
    float s = 0.0f;
#pragma unroll
    for (int sp = 0; sp < SPLITK; sp++) s += p[(size_t)sp * C_DIM * C_DIM];
    g_qv[j] = f2tf32f(s);
}

// ---------------------------------------------------------------------------
// C: m[b] = Wo @ qv[b]   (NN, 256^3) -> tf32
// ---------------------------------------------------------------------------
__global__ void __launch_bounds__(256, 2)
wo_qv_kernel()
{
    __shared__ uint32_t smem[SMEM_WORDS];
    const int b  = blockIdx.z;
    const int m0 = blockIdx.y * 128;
    const int n0 = blockIdx.x * 128;

    const float* A = g_Wo + (size_t)m0 * C_DIM;
    const float* B = g_qv + (size_t)b * C_DIM * C_DIM + n0;

    float c[2][8][4];
    ACC_INIT(c)
    gemm_core<false>(A, B, C_DIM, C_DIM, C_DIM, c, smem);

    float* Cb = g_m + (size_t)b * C_DIM * C_DIM;

    const int lane = threadIdx.x & 31;
    const int wid  = threadIdx.x >> 5;
    const int g    = lane >> 2;
    const int t    = lane & 3;
    const int wm   = (wid & 3) * 32;
    const int wn   = (wid >> 2) * 64;

#pragma unroll
    for (int mi = 0; mi < 2; mi++)
#pragma unroll
        for (int ni = 0; ni < 8; ni++) {
            const int col = n0 + wn + ni * 8 + 2 * t;
#pragma unroll
            for (int h = 0; h < 2; h++) {
                const int row = m0 + wm + mi * 16 + g + h * 8;
                float2 o;
                o.x = f2tf32f(c[mi][ni][2 * h + 0]);
                o.y = f2tf32f(c[mi][ni][2 * h + 1]);
                *(float2*)(Cb + (size_t)row * C_DIM + col) = o;
            }
        }
}

// ---------------------------------------------------------------------------
// D: out[b] = m[b] @ phi_k[b] + bo   (NN, M=256, N=4096, K=256), fp32 out
// ---------------------------------------------------------------------------
__global__ void __launch_bounds__(256, 2)
out_kernel(const float* __restrict__ bo, float* __restrict__ out)
{
    __shared__ uint32_t smem[SMEM_WORDS];
    const int b  = blockIdx.z;
    const int m0 = blockIdx.y * 128;
    const int n0 = blockIdx.x * 128;

    const float* A = g_m + (size_t)b * C_DIM * C_DIM + (size_t)m0 * C_DIM;
    const float* B = g_phi_k + (size_t)b * C_DIM * NPIX + n0;

    float c[2][8][4];
    ACC_INIT(c)
    gemm_core<false>(A, B, C_DIM, C_DIM, NPIX, c, smem);

    float* Ob = out + (size_t)b * C_DIM * NPIX;

    const int lane = threadIdx.x & 31;
    const int wid  = threadIdx.x >> 5;
    const int g    = lane >> 2;
    const int t    = lane & 3;
    const int wm   = (wid & 3) * 32;
    const int wn   = (wid >> 2) * 64;

#pragma unroll
    for (int mi = 0; mi < 2; mi++)
#pragma unroll
        for (int ni = 0; ni < 8; ni++) {
            const int col = n0 + wn + ni * 8 + 2 * t;
#pragma unroll
            for (int h = 0; h < 2; h++) {
                const int row = m0 + wm + mi * 16 + g + h * 8;
                const float bi = bo[row];
                float2 o;
                o.x = c[mi][ni][2 * h + 0] + bi;
                o.y = c[mi][ni][2 * h + 1] + bi;
                *(float2*)(Ob + (size_t)row * NPIX + col) = o;
            }
        }
}

// ---------------------------------------------------------------------------
// Launch (no cudaFuncSetAttribute, no dynamic smem — guard-safe host path)
// ---------------------------------------------------------------------------
extern "C" void kernel_launch(void* const* d_in, const int* in_sizes, int n_in,
                              void* d_out, int out_size)
{
    const float* x  = (const float*)d_in[0];
    const float* Wq = (const float*)d_in[1];
    const float* Wk = (const float*)d_in[2];
    const float* Wv = (const float*)d_in[3];
    const float* Wo = (const float*)d_in[4];
    const float* bo = (const float*)d_in[5];
    float* out = (float*)d_out;

    pack_w<<<C_DIM * C_DIM / 256, 256>>>(Wq, Wk, Wv, Wo);
    cvt_x_kernel<<<BATCH * C_DIM * NPIX / 1024, 256>>>(x);

    // A: QKV + phi — grid (32, 6, 16)
    qkv_kernel<<<dim3(NPIX / 128, 3 * C_DIM / 128, BATCH), 256>>>();

    // B: qv split-K partials — grid (2, 2, 128)
    qv_kernel<<<dim3(C_DIM / 128, C_DIM / 128, BATCH * SPLITK), 256>>>();
    qv_reduce<<<BATCH * C_DIM * C_DIM / 256, 256>>>();

    // C: m = Wo @ qv — grid (2, 2, 16)
    wo_qv_kernel<<<dim3(C_DIM / 128, C_DIM / 128, BATCH), 256>>>();

    // D: out = m @ phi_k + bo — grid (32, 2, 16)
    out_kernel<<<dim3(NPIX / 128, C_DIM / 128, BATCH), 256>>>(bo, out);
}

// round 8
// speedup vs baseline: 5.8039x; 1.7317x over previous
#include <cuda_runtime.h>
#include <cuda_fp16.h>
#include <cstdint>

#define C_DIM  256
#define NPIX   4096
#define BATCH  16
#define SPLITK 8

// ---------------------------------------------------------------------------
// Scratch (__device__ globals; allocation-free rule)
// ---------------------------------------------------------------------------
__device__ __align__(16) __half g_Wqkv[3 * C_DIM * C_DIM];   // fp16 packed [768][256]
__device__ __align__(16) __half g_Wo  [C_DIM * C_DIM];
__device__ __align__(16) __half g_x   [BATCH * C_DIM * NPIX];   // 32 MB
__device__ __align__(16) __half g_phi_q[BATCH * C_DIM * NPIX];  // 32 MB
__device__ __align__(16) __half g_phi_k[BATCH * C_DIM * NPIX];
__device__ __align__(16) __half g_phi_v[BATCH * C_DIM * NPIX];
__device__ float  g_qvp[SPLITK * BATCH * C_DIM * C_DIM];        // fp32 partials
__device__ __align__(16) __half g_qv  [BATCH * C_DIM * C_DIM];
__device__ __align__(16) __half g_m   [BATCH * C_DIM * C_DIM];

__device__ __forceinline__ float phi_f(float x) {
    return x > 0.0f ? x + 1.0f : __expf(x);
}

__device__ __forceinline__ void mma_f16(float c[4], const uint32_t a[4],
                                        uint32_t b0, uint32_t b1) {
    asm volatile(
        "mma.sync.aligned.m16n8k16.row.col.f32.f16.f16.f32 "
        "{%0,%1,%2,%3},{%4,%5,%6,%7},{%8,%9},{%0,%1,%2,%3};"
        : "+f"(c[0]), "+f"(c[1]), "+f"(c[2]), "+f"(c[3])
        : "r"(a[0]), "r"(a[1]), "r"(a[2]), "r"(a[3]), "r"(b0), "r"(b1));
}

__device__ __forceinline__ void ldsm_x4(uint32_t& r0, uint32_t& r1,
                                        uint32_t& r2, uint32_t& r3, uint32_t addr) {
    asm volatile("ldmatrix.sync.aligned.m8n8.x4.shared.b16 {%0,%1,%2,%3}, [%4];"
                 : "=r"(r0), "=r"(r1), "=r"(r2), "=r"(r3) : "r"(addr));
}
__device__ __forceinline__ void ldsm_x4_t(uint32_t& r0, uint32_t& r1,
                                          uint32_t& r2, uint32_t& r3, uint32_t addr) {
    asm volatile("ldmatrix.sync.aligned.m8n8.x4.trans.shared.b16 {%0,%1,%2,%3}, [%4];"
                 : "=r"(r0), "=r"(r1), "=r"(r2), "=r"(r3) : "r"(addr));
}

__device__ __forceinline__ void cpa16(uint32_t saddr, const void* gptr) {
    asm volatile("cp.async.cg.shared.global [%0], [%1], 16;"
                 :: "r"(saddr), "l"(gptr));
}
__device__ __forceinline__ void cpa_commit() {
    asm volatile("cp.async.commit_group;");
}
template<int N>
__device__ __forceinline__ void cpa_wait() {
    asm volatile("cp.async.wait_group %0;" :: "n"(N));
}

// ---------------------------------------------------------------------------
// fp16 GEMM core: BM=128, BN=128, BK=32, 256 threads = 8 warps (4m x 2n),
// warp tile 32x64 -> 2 m-subtiles x 8 n-subtiles of m16n8k16.
// Double-buffered cp.async, static 40KB smem, ldmatrix fragment loads.
// BT=false: B is [K][N] fp16 (pre-offset by n0 cols).
// BT=true : B is [N][K] fp16 (pre-offset by n0 rows).
// ---------------------------------------------------------------------------
#define LDA_H 40                         // halves: 32 + 8 pad (80B rows)
#define LDB_H 136                        // halves: 128 + 8 pad (272B rows, NN)
#define A_BYTES (128 * LDA_H * 2)        // 10240
#define B_BYTES (128 * LDA_H * 2)        // 10240 (NN uses 32*136*2 = 8704)
#define STAGE_BYTES (A_BYTES + B_BYTES)  // 20480
#define SMEM_BYTES (2 * STAGE_BYTES)     // 40960 (static, no opt-in)

template<bool BT>
__device__ __forceinline__ void gemm_core(const __half* __restrict__ A,
                                          const __half* __restrict__ B,
                                          int K, int lda, int ldb,
                                          float c[2][8][4], char* smem_raw)
{
    const uint32_t smem_u = (uint32_t)__cvta_generic_to_shared(smem_raw);

    const int tid  = threadIdx.x;
    const int lane = tid & 31;
    const int wid  = tid >> 5;
    const int wm   = (wid & 3) * 32;
    const int wn   = (wid >> 2) * 64;

    // ldmatrix lane decomposition
    const int lrow = lane & 7;
    const int sel  = lane >> 3;          // 0..3
    const int selr = (sel & 1) << 3;     // +8 rows
    const int selc = (sel >> 1) << 3;    // +8 k (or +8 n halves for NN chunks)

    // cp.async per-thread coordinates
    const int ar  = tid >> 2;            // 0..63 (stride 64 over p): A/BT rows
    const int ac8 = (tid & 3) << 3;      // halves 0,8,16,24
    const int br  = tid >> 4;            // 0..15 (stride 16 over p): NN k rows
    const int bc8 = (tid & 15) << 3;     // halves 0..120

    const int niter = K >> 5;

    auto load_stage = [&](int s, int k0) {
        const uint32_t sa = smem_u + (uint32_t)(s * STAGE_BYTES);
        const uint32_t sb = sa + A_BYTES;
#pragma unroll
        for (int p = 0; p < 2; p++) {
            const int r = ar + p * 64;
            cpa16(sa + (uint32_t)(r * LDA_H + ac8) * 2,
                  A + (size_t)r * lda + k0 + ac8);
        }
        if (BT) {
#pragma unroll
            for (int p = 0; p < 2; p++) {
                const int r = ar + p * 64;
                cpa16(sb + (uint32_t)(r * LDA_H + ac8) * 2,
                      B + (size_t)r * ldb + k0 + ac8);
            }
        } else {
#pragma unroll
            for (int p = 0; p < 2; p++) {
                const int r = br + p * 16;
                cpa16(sb + (uint32_t)(r * LDB_H + bc8) * 2,
                      B + (size_t)(k0 + r) * ldb + bc8);
            }
        }
        cpa_commit();
    };

    load_stage(0, 0);

    for (int it = 0; it < niter; it++) {
        if (it + 1 < niter) {
            load_stage((it + 1) & 1, (it + 1) << 5);
            cpa_wait<1>();
        } else {
            cpa_wait<0>();
        }
        __syncthreads();

        const uint32_t sa = smem_u + (uint32_t)((it & 1) * STAGE_BYTES);
        const uint32_t sb = sa + A_BYTES;

#pragma unroll
        for (int ks = 0; ks < 32; ks += 16) {
            // ---- A fragments: 2 x ldmatrix.x4 ----
            uint32_t a[2][4];
#pragma unroll
            for (int mi = 0; mi < 2; mi++) {
                const int row = wm + mi * 16 + selr + lrow;
                ldsm_x4(a[mi][0], a[mi][1], a[mi][2], a[mi][3],
                        sa + (uint32_t)(row * LDA_H + ks + selc) * 2);
            }
            // ---- B fragments: 4 x ldmatrix.x4 ----
            uint32_t b0v[8], b1v[8];
#pragma unroll
            for (int p = 0; p < 4; p++) {
                const int nb = wn + p * 16;
                uint32_t r0, r1, r2, r3;
                if (BT) {
                    const int row = nb + selr + lrow;
                    ldsm_x4(r0, r1, r2, r3,
                            sb + (uint32_t)(row * LDA_H + ks + selc) * 2);
                    b0v[2*p] = r0; b0v[2*p+1] = r1;
                    b1v[2*p] = r2; b1v[2*p+1] = r3;
                } else {
                    const int krow = ks + selr + lrow;
                    ldsm_x4_t(r0, r1, r2, r3,
                              sb + (uint32_t)(krow * LDB_H + nb + selc) * 2);
                    b0v[2*p] = r0; b1v[2*p] = r1;
                    b0v[2*p+1] = r2; b1v[2*p+1] = r3;
                }
            }
#pragma unroll
            for (int ni = 0; ni < 8; ni++) {
                mma_f16(c[0][ni], a[0], b0v[ni], b1v[ni]);
                mma_f16(c[1][ni], a[1], b0v[ni], b1v[ni]);
            }
        }
        __syncthreads();
    }
}

#define ACC_INIT(c)                                   \
    _Pragma("unroll")                                 \
    for (int mi = 0; mi < 2; mi++)                    \
        _Pragma("unroll")                             \
        for (int ni = 0; ni < 8; ni++)                \
            _Pragma("unroll")                         \
            for (int e = 0; e < 4; e++) c[mi][ni][e] = 0.0f;

#define EPILOGUE_COORDS                               \
    const int lane = threadIdx.x & 31;                \
    const int wid  = threadIdx.x >> 5;                \
    const int g    = lane >> 2;                       \
    const int t    = lane & 3;                        \
    const int wm   = (wid & 3) * 32;                  \
    const int wn   = (wid >> 2) * 64;

// ---------------------------------------------------------------------------
// Prep kernels: fp32 -> fp16
// ---------------------------------------------------------------------------
__global__ void pack_w(const float* __restrict__ q, const float* __restrict__ k,
                       const float* __restrict__ v, const float* __restrict__ o)
{
    const int i = blockIdx.x * 256 + threadIdx.x;
    g_Wqkv[i]                     = __float2half_rn(q[i]);
    g_Wqkv[C_DIM * C_DIM + i]     = __float2half_rn(k[i]);
    g_Wqkv[2 * C_DIM * C_DIM + i] = __float2half_rn(v[i]);
    g_Wo[i]                       = __float2half_rn(o[i]);
}

__global__ void cvt_x_kernel(const float* __restrict__ x)
{
    const size_t i = ((size_t)blockIdx.x * 256 + threadIdx.x) * 4;
    const float4 v = *(const float4*)(x + i);
    __half2 h0 = __floats2half2_rn(v.x, v.y);
    __half2 h1 = __floats2half2_rn(v.z, v.w);
    uint2 u;
    u.x = *(uint32_t*)&h0;
    u.y = *(uint32_t*)&h1;
    *(uint2*)(g_x + i) = u;
}

// ---------------------------------------------------------------------------
// A: Wqkv[768x256] @ x[b][256x4096] -> phi -> fp16 -> g_phi_{q,k,v}
// ---------------------------------------------------------------------------
__global__ void __launch_bounds__(256, 2)
qkv_kernel()
{
    __shared__ __align__(16) char smem[SMEM_BYTES];
    const int b  = blockIdx.z;
    const int m0 = blockIdx.y * 128;
    const int n0 = blockIdx.x * 128;

    const __half* A = g_Wqkv + (size_t)m0 * C_DIM;
    const __half* B = g_x + (size_t)b * C_DIM * NPIX + n0;

    float c[2][8][4];
    ACC_INIT(c)
    gemm_core<false>(A, B, C_DIM, C_DIM, NPIX, c, smem);

    __half* bufs[3] = {g_phi_q, g_phi_k, g_phi_v};
    __half* Ob = bufs[m0 >> 8] + (size_t)b * C_DIM * NPIX;
    const int rowc0 = m0 & 255;

    EPILOGUE_COORDS
#pragma unroll
    for (int mi = 0; mi < 2; mi++)
#pragma unroll
        for (int ni = 0; ni < 8; ni++) {
            const int col = n0 + wn + ni * 8 + 2 * t;
#pragma unroll
            for (int h = 0; h < 2; h++) {
                const int row = rowc0 + wm + mi * 16 + g + h * 8;
                __half2 o = __floats2half2_rn(phi_f(c[mi][ni][2 * h + 0]),
                                              phi_f(c[mi][ni][2 * h + 1]));
                *(uint32_t*)(Ob + (size_t)row * NPIX + col) = *(uint32_t*)&o;
            }
        }
}

// ---------------------------------------------------------------------------
// B: split-K qv partials: g_qvp[b*8+sp] = phi_q[b][:, sp*512:+512] @ phi_v^T
// ---------------------------------------------------------------------------
__global__ void __launch_bounds__(256, 2)
qv_kernel()
{
    __shared__ __align__(16) char smem[SMEM_BYTES];
    const int z  = blockIdx.z;
    const int b  = z >> 3;
    const int sp = z & 7;
    const int m0 = blockIdx.y * 128;
    const int n0 = blockIdx.x * 128;
    const int kofs = sp * (NPIX / SPLITK);

    const __half* A = g_phi_q + (size_t)b * C_DIM * NPIX + (size_t)m0 * NPIX + kofs;
    const __half* B = g_phi_v + (size_t)b * C_DIM * NPIX + (size_t)n0 * NPIX + kofs;

    float c[2][8][4];
    ACC_INIT(c)
    gemm_core<true>(A, B, NPIX / SPLITK, NPIX, NPIX, c, smem);

    float* Cb = g_qvp + (size_t)z * C_DIM * C_DIM;

    EPILOGUE_COORDS
#pragma unroll
    for (int mi = 0; mi < 2; mi++)
#pragma unroll
        for (int ni = 0; ni < 8; ni++) {
            const int col = n0 + wn + ni * 8 + 2 * t;
#pragma unroll
            for (int h = 0; h < 2; h++) {
                const int row = m0 + wm + mi * 16 + g + h * 8;
                float2 o;
                o.x = c[mi][ni][2 * h + 0];
                o.y = c[mi][ni][2 * h + 1];
                *(float2*)(Cb + (size_t)row * C_DIM + col) = o;
            }
        }
}

// Deterministic fixed-order reduction -> fp16
__global__ void qv_reduce()
{
    const int j = blockIdx.x * 256 + threadIdx.x;
    const int b = j >> 16;
    const int i = j & 65535;
    const float* p = g_qvp + (size_t)b * SPLITK * C_DIM * C_DIM + i;
    float s = 0.0f;
#pragma unroll
    for (int sp = 0; sp < SPLITK; sp++) s += p[(size_t)sp * C_DIM * C_DIM];
    g_qv[j] = __float2half_rn(s);
}

// ---------------------------------------------------------------------------
// C: m[b] = Wo @ qv[b]   (NN, 256^3) -> fp16
// ---------------------------------------------------------------------------
__global__ void __launch_bounds__(256, 2)
wo_qv_kernel()
{
    __shared__ __align__(16) char smem[SMEM_BYTES];
    const int b  = blockIdx.z;
    const int m0 = blockIdx.y * 128;
    const int n0 = blockIdx.x * 128;

    const __half* A = g_Wo + (size_t)m0 * C_DIM;
    const __half* B = g_qv + (size_t)b * C_DIM * C_DIM + n0;

    float c[2][8][4];
    ACC_INIT(c)
    gemm_core<false>(A, B, C_DIM, C_DIM, C_DIM, c, smem);

    __half* Cb = g_m + (size_t)b * C_DIM * C_DIM;

    EPILOGUE_COORDS
#pragma unroll
    for (int mi = 0; mi < 2; mi++)
#pragma unroll
        for (int ni = 0; ni < 8; ni++) {
            const int col = n0 + wn + ni * 8 + 2 * t;
#pragma unroll
            for (int h = 0; h < 2; h++) {
                const int row = m0 + wm + mi * 16 + g + h * 8;
                __half2 o = __floats2half2_rn(c[mi][ni][2 * h + 0],
                                              c[mi][ni][2 * h + 1]);
                *(uint32_t*)(Cb + (size_t)row * C_DIM + col) = *(uint32_t*)&o;
            }
        }
}

// ---------------------------------------------------------------------------
// D: out[b] = m[b] @ phi_k[b] + bo   (NN, M=256, N=4096, K=256), fp32 out
// ---------------------------------------------------------------------------
__global__ void __launch_bounds__(256, 2)
out_kernel(const float* __restrict__ bo, float* __restrict__ out)
{
    __shared__ __align__(16) char smem[SMEM_BYTES];
    const int b  = blockIdx.z;
    const int m0 = blockIdx.y * 128;
    const int n0 = blockIdx.x * 128;

    const __half* A = g_m + (size_t)b * C_DIM * C_DIM + (size_t)m0 * C_DIM;
    const __half* B = g_phi_k + (size_t)b * C_DIM * NPIX + n0;

    float c[2][8][4];
    ACC_INIT(c)
    gemm_core<false>(A, B, C_DIM, C_DIM, NPIX, c, smem);

    float* Ob = out + (size_t)b * C_DIM * NPIX;

    EPILOGUE_COORDS
#pragma unroll
    for (int mi = 0; mi < 2; mi++)
#pragma unroll
        for (int ni = 0; ni < 8; ni++) {
            const int col = n0 + wn + ni * 8 + 2 * t;
#pragma unroll
            for (int h = 0; h < 2; h++) {
                const int row = m0 + wm + mi * 16 + g + h * 8;
                const float bi = bo[row];
                float2 o;
                o.x = c[mi][ni][2 * h + 0] + bi;
                o.y = c[mi][ni][2 * h + 1] + bi;
                *(float2*)(Ob + (size_t)row * NPIX + col) = o;
            }
        }
}

// ---------------------------------------------------------------------------
// Launch (guard-safe: no attribute calls, static smem only)
// ---------------------------------------------------------------------------
extern "C" void kernel_launch(void* const* d_in, const int* in_sizes, int n_in,
                              void* d_out, int out_size)
{
    const float* x  = (const float*)d_in[0];
    const float* Wq = (const float*)d_in[1];
    const float* Wk = (const float*)d_in[2];
    const float* Wv = (const float*)d_in[3];
    const float* Wo = (const float*)d_in[4];
    const float* bo = (const float*)d_in[5];
    float* out = (float*)d_out;

    pack_w<<<C_DIM * C_DIM / 256, 256>>>(Wq, Wk, Wv, Wo);
    cvt_x_kernel<<<BATCH * C_DIM * NPIX / 1024, 256>>>(x);

    // A: QKV + phi — grid (32, 6, 16)
    qkv_kernel<<<dim3(NPIX / 128, 3 * C_DIM / 128, BATCH), 256>>>();

    // B: qv split-K partials — grid (2, 2, 128)
    qv_kernel<<<dim3(C_DIM / 128, C_DIM / 128, BATCH * SPLITK), 256>>>();
    qv_reduce<<<BATCH * C_DIM * C_DIM / 256, 256>>>();

    // C: m = Wo @ qv — grid (2, 2, 16)
    wo_qv_kernel<<<dim3(C_DIM / 128, C_DIM / 128, BATCH), 256>>>();

    // D: out = m @ phi_k + bo — grid (32, 2, 16)
    out_kernel<<<dim3(NPIX / 128, C_DIM / 128, BATCH), 256>>>(bo, out);
}

// round 11
// speedup vs baseline: 5.9043x; 1.0173x over previous
#include <cuda_runtime.h>
#include <cuda_fp16.h>
#include <cstdint>

#define C_DIM  256
#define NPIX   4096
#define BATCH  16
#define SPLITK 4

// ---------------------------------------------------------------------------
// Scratch (__device__ globals; allocation-free rule)
// ---------------------------------------------------------------------------
__device__ __align__(16) __half g_Wqkv[3 * C_DIM * C_DIM];   // fp16 packed [768][256]
__device__ __align__(16) __half g_Wo  [C_DIM * C_DIM];
__device__ __align__(16) __half g_x   [BATCH * C_DIM * NPIX];   // 32 MB
__device__ __align__(16) __half g_phi_q[BATCH * C_DIM * NPIX];
__device__ __align__(16) __half g_phi_k[BATCH * C_DIM * NPIX];
__device__ __align__(16) __half g_phi_v[BATCH * C_DIM * NPIX];
__device__ float  g_qvp[SPLITK * BATCH * C_DIM * C_DIM];        // fp32 partials
__device__ __align__(16) __half g_qv  [BATCH * C_DIM * C_DIM];
__device__ __align__(16) __half g_m   [BATCH * C_DIM * C_DIM];

__device__ __forceinline__ float phi_f(float x) {
    return x > 0.0f ? x + 1.0f : __expf(x);
}

__device__ __forceinline__ void mma_f16(float c[4], const uint32_t a[4],
                                        uint32_t b0, uint32_t b1) {
    asm volatile(
        "mma.sync.aligned.m16n8k16.row.col.f32.f16.f16.f32 "
        "{%0,%1,%2,%3},{%4,%5,%6,%7},{%8,%9},{%0,%1,%2,%3};"
        : "+f"(c[0]), "+f"(c[1]), "+f"(c[2]), "+f"(c[3])
        : "r"(a[0]), "r"(a[1]), "r"(a[2]), "r"(a[3]), "r"(b0), "r"(b1));
}

__device__ __forceinline__ void ldsm_x4(uint32_t& r0, uint32_t& r1,
                                        uint32_t& r2, uint32_t& r3, uint32_t addr) {
    asm volatile("ldmatrix.sync.aligned.m8n8.x4.shared.b16 {%0,%1,%2,%3}, [%4];"
                 : "=r"(r0), "=r"(r1), "=r"(r2), "=r"(r3) : "r"(addr));
}
__device__ __forceinline__ void ldsm_x4_t(uint32_t& r0, uint32_t& r1,
                                          uint32_t& r2, uint32_t& r3, uint32_t addr) {
    asm volatile("ldmatrix.sync.aligned.m8n8.x4.trans.shared.b16 {%0,%1,%2,%3}, [%4];"
                 : "=r"(r0), "=r"(r1), "=r"(r2), "=r"(r3) : "r"(addr));
}

__device__ __forceinline__ void cpa16(uint32_t saddr, const void* gptr) {
    asm volatile("cp.async.cg.shared.global [%0], [%1], 16;"
                 :: "r"(saddr), "l"(gptr));
}
__device__ __forceinline__ void cpa_commit() {
    asm volatile("cp.async.commit_group;");
}
template<int N>
__device__ __forceinline__ void cpa_wait() {
    asm volatile("cp.async.wait_group %0;" :: "n"(N));
}

// ---------------------------------------------------------------------------
// fp16 GEMM core: BM=64, BN=128, BK=32, 128 threads = 4 warps (2m x 2n),
// warp tile 32x64 -> 2 m-subtiles x 8 n-subtiles of m16n8k16.
// Double-buffered cp.async, static 30KB smem, ldmatrix fragment loads.
// 4 CTAs/SM (independent barrier domains) hide barrier + load latency.
// BT=false: B is [K][N] fp16 (pre-offset by n0 cols).
// BT=true : B is [N][K] fp16 (pre-offset by n0 rows).
// ---------------------------------------------------------------------------
#define LDA_H 40                         // halves: 32 + 8 pad (80B rows, conflict-free)
#define LDB_H 136                        // halves: 128 + 8 pad (272B rows, NN)
#define A_BYTES (64 * LDA_H * 2)         // 5120
#define B_BYTES (128 * LDA_H * 2)        // 10240 (NN uses 32*136*2 = 8704)
#define STAGE_BYTES (A_BYTES + B_BYTES)  // 15360
#define SMEM_BYTES (2 * STAGE_BYTES)     // 30720 (static, no opt-in)

template<bool BT>
__device__ __forceinline__ void gemm_core(const __half* __restrict__ A,
                                          const __half* __restrict__ B,
                                          int K, int lda, int ldb,
                                          float c[2][8][4], char* smem_raw)
{
    const uint32_t smem_u = (uint32_t)__cvta_generic_to_shared(smem_raw);

    const int tid  = threadIdx.x;
    const int lane = tid & 31;
    const int wid  = tid >> 5;           // 0..3
    const int wm   = (wid & 1) * 32;
    const int wn   = (wid >> 1) * 64;

    // ldmatrix lane decomposition
    const int lrow = lane & 7;
    const int sel  = lane >> 3;          // 0..3
    const int selr = (sel & 1) << 3;     // +8 rows
    const int selc = (sel >> 1) << 3;    // +8 k (or +8 n halves for NN)

    // cp.async per-thread coordinates
    const int ar  = tid >> 2;            // 0..31
    const int ac8 = (tid & 3) << 3;      // halves 0,8,16,24
    const int br  = tid >> 4;            // 0..7 (NN k rows, stride 8)
    const int bc8 = (tid & 15) << 3;     // halves 0..120

    const int niter = K >> 5;

    auto load_stage = [&](int s, int k0) {
        const uint32_t sa = smem_u + (uint32_t)(s * STAGE_BYTES);
        const uint32_t sb = sa + A_BYTES;
        // A: 64 rows x 32 halves -> 2 chunks/thread
#pragma unroll
        for (int p = 0; p < 2; p++) {
            const int r = ar + p * 32;
            cpa16(sa + (uint32_t)(r * LDA_H + ac8) * 2,
                  A + (size_t)r * lda + k0 + ac8);
        }
        if (BT) {
            // B: 128 rows x 32 halves -> 4 chunks/thread
#pragma unroll
            for (int p = 0; p < 4; p++) {
                const int r = ar + p * 32;
                cpa16(sb + (uint32_t)(r * LDA_H + ac8) * 2,
                      B + (size_t)r * ldb + k0 + ac8);
            }
        } else {
            // B: 32 k-rows x 128 halves -> 4 chunks/thread
#pragma unroll
            for (int p = 0; p < 4; p++) {
                const int r = br + p * 8;
                cpa16(sb + (uint32_t)(r * LDB_H + bc8) * 2,
                      B + (size_t)(k0 + r) * ldb + bc8);
            }
        }
        cpa_commit();
    };

    load_stage(0, 0);

    for (int it = 0; it < niter; it++) {
        if (it + 1 < niter) {
            load_stage((it + 1) & 1, (it + 1) << 5);
            cpa_wait<1>();
        } else {
            cpa_wait<0>();
        }
        __syncthreads();

        const uint32_t sa = smem_u + (uint32_t)((it & 1) * STAGE_BYTES);
        const uint32_t sb = sa + A_BYTES;

#pragma unroll
        for (int ks = 0; ks < 32; ks += 16) {
            // ---- A fragments: 2 x ldmatrix.x4 ----
            uint32_t a[2][4];
#pragma unroll
            for (int mi = 0; mi < 2; mi++) {
                const int row = wm + mi * 16 + selr + lrow;
                ldsm_x4(a[mi][0], a[mi][1], a[mi][2], a[mi][3],
                        sa + (uint32_t)(row * LDA_H + ks + selc) * 2);
            }
            // ---- B fragments: 4 x ldmatrix.x4 ----
            uint32_t b0v[8], b1v[8];
#pragma unroll
            for (int p = 0; p < 4; p++) {
                const int nb = wn + p * 16;
                uint32_t r0, r1, r2, r3;
                if (BT) {
                    const int row = nb + selr + lrow;
                    ldsm_x4(r0, r1, r2, r3,
                            sb + (uint32_t)(row * LDA_H + ks + selc) * 2);
                    b0v[2*p] = r0; b0v[2*p+1] = r1;
                    b1v[2*p] = r2; b1v[2*p+1] = r3;
                } else {
                    const int krow = ks + selr + lrow;
                    ldsm_x4_t(r0, r1, r2, r3,
                              sb + (uint32_t)(krow * LDB_H + nb + selc) * 2);
                    b0v[2*p] = r0; b1v[2*p] = r1;
                    b0v[2*p+1] = r2; b1v[2*p+1] = r3;
                }
            }
#pragma unroll
            for (int ni = 0; ni < 8; ni++) {
                mma_f16(c[0][ni], a[0], b0v[ni], b1v[ni]);
                mma_f16(c[1][ni], a[1], b0v[ni], b1v[ni]);
            }
        }
        __syncthreads();
    }
}

#define ACC_INIT(c)                                   \
    _Pragma("unroll")                                 \
    for (int mi = 0; mi < 2; mi++)                    \
        _Pragma("unroll")                             \
        for (int ni = 0; ni < 8; ni++)                \
            _Pragma("unroll")                         \
            for (int e = 0; e < 4; e++) c[mi][ni][e] = 0.0f;

#define EPILOGUE_COORDS                               \
    const int lane = threadIdx.x & 31;                \
    const int wid  = threadIdx.x >> 5;                \
    const int g    = lane >> 2;                       \
    const int t    = lane & 3;                        \
    const int wm   = (wid & 1) * 32;                  \
    const int wn   = (wid >> 1) * 64;

// ---------------------------------------------------------------------------
// Prep kernels: fp32 -> fp16
// ---------------------------------------------------------------------------
__global__ void pack_w(const float* __restrict__ q, const float* __restrict__ k,
                       const float* __restrict__ v, const float* __restrict__ o)
{
    const int i = blockIdx.x * 256 + threadIdx.x;
    g_Wqkv[i]                     = __float2half_rn(q[i]);
    g_Wqkv[C_DIM * C_DIM + i]     = __float2half_rn(k[i]);
    g_Wqkv[2 * C_DIM * C_DIM + i] = __float2half_rn(v[i]);
    g_Wo[i]                       = __float2half_rn(o[i]);
}

__global__ void cvt_x_kernel(const float* __restrict__ x)
{
    const size_t i = ((size_t)blockIdx.x * 256 + threadIdx.x) * 4;
    const float4 v = *(const float4*)(x + i);
    __half2 h0 = __floats2half2_rn(v.x, v.y);
    __half2 h1 = __floats2half2_rn(v.z, v.w);
    uint2 u;
    u.x = *(uint32_t*)&h0;
    u.y = *(uint32_t*)&h1;
    *(uint2*)(g_x + i) = u;
}

// ---------------------------------------------------------------------------
// A: Wqkv[768x256] @ x[b][256x4096] -> phi -> fp16 -> g_phi_{q,k,v}
// grid (32, 12, 16), 128 threads
// ---------------------------------------------------------------------------
__global__ void __launch_bounds__(128, 4)
qkv_kernel()
{
    __shared__ __align__(16) char smem[SMEM_BYTES];
    const int b  = blockIdx.z;
    const int m0 = blockIdx.y * 64;      // 0..704 within [768]
    const int n0 = blockIdx.x * 128;

    const __half* A = g_Wqkv + (size_t)m0 * C_DIM;
    const __half* B = g_x + (size_t)b * C_DIM * NPIX + n0;

    float c[2][8][4];
    ACC_INIT(c)
    gemm_core<false>(A, B, C_DIM, C_DIM, NPIX, c, smem);

    __half* bufs[3] = {g_phi_q, g_phi_k, g_phi_v};
    __half* Ob = bufs[m0 >> 8] + (size_t)b * C_DIM * NPIX;
    const int rowc0 = m0 & 255;

    EPILOGUE_COORDS
#pragma unroll
    for (int mi = 0; mi < 2; mi++)
#pragma unroll
        for (int ni = 0; ni < 8; ni++) {
            const int col = n0 + wn + ni * 8 + 2 * t;
#pragma unroll
            for (int h = 0; h < 2; h++) {
                const int row = rowc0 + wm + mi * 16 + g + h * 8;
                __half2 o = __floats2half2_rn(phi_f(c[mi][ni][2 * h + 0]),
                                              phi_f(c[mi][ni][2 * h + 1]));
                *(uint32_t*)(Ob + (size_t)row * NPIX + col) = *(uint32_t*)&o;
            }
        }
}

// ---------------------------------------------------------------------------
// B: split-K qv partials: g_qvp[b*4+sp] = phi_q[b][:, sp*1024:+1024] @ phi_v^T
// grid (2, 4, 64), 128 threads
// ---------------------------------------------------------------------------
__global__ void __launch_bounds__(128, 4)
qv_kernel()
{
    __shared__ __align__(16) char smem[SMEM_BYTES];
    const int z  = blockIdx.z;
    const int b  = z >> 2;
    const int sp = z & 3;
    const int m0 = blockIdx.y * 64;
    const int n0 = blockIdx.x * 128;
    const int kofs = sp * (NPIX / SPLITK);

    const __half* A = g_phi_q + (size_t)b * C_DIM * NPIX + (size_t)m0 * NPIX + kofs;
    const __half* B = g_phi_v + (size_t)b * C_DIM * NPIX + (size_t)n0 * NPIX + kofs;

    float c[2][8][4];
    ACC_INIT(c)
    gemm_core<true>(A, B, NPIX / SPLITK, NPIX, NPIX, c, smem);

    float* Cb = g_qvp + (size_t)z * C_DIM * C_DIM;

    EPILOGUE_COORDS
#pragma unroll
    for (int mi = 0; mi < 2; mi++)
#pragma unroll
        for (int ni = 0; ni < 8; ni++) {
            const int col = n0 + wn + ni * 8 + 2 * t;
#pragma unroll
            for (int h = 0; h < 2; h++) {
                const int row = m0 + wm + mi * 16 + g + h * 8;
                float2 o;
                o.x = c[mi][ni][2 * h + 0];
                o.y = c[mi][ni][2 * h + 1];
                *(float2*)(Cb + (size_t)row * C_DIM + col) = o;
            }
        }
}

// Deterministic fixed-order reduction -> fp16
__global__ void qv_reduce()
{
    const int j = blockIdx.x * 256 + threadIdx.x;
    const int b = j >> 16;
    const int i = j & 65535;
    const float* p = g_qvp + (size_t)b * SPLITK * C_DIM * C_DIM + i;
    float s = 0.0f;
#pragma unroll
    for (int sp = 0; sp < SPLITK; sp++) s += p[(size_t)sp * C_DIM * C_DIM];
    g_qv[j] = __float2half_rn(s);
}

// ---------------------------------------------------------------------------
// C: m[b] = Wo @ qv[b]   (NN, 256^3) -> fp16
// grid (2, 4, 16)
// ---------------------------------------------------------------------------
__global__ void __launch_bounds__(128, 4)
wo_qv_kernel()
{
    __shared__ __align__(16) char smem[SMEM_BYTES];
    const int b  = blockIdx.z;
    const int m0 = blockIdx.y * 64;
    const int n0 = blockIdx.x * 128;

    const __half* A = g_Wo + (size_t)m0 * C_DIM;
    const __half* B = g_qv + (size_t)b * C_DIM * C_DIM + n0;

    float c[2][8][4];
    ACC_INIT(c)
    gemm_core<false>(A, B, C_DIM, C_DIM, C_DIM, c, smem);

    __half* Cb = g_m + (size_t)b * C_DIM * C_DIM;

    EPILOGUE_COORDS
#pragma unroll
    for (int mi = 0; mi < 2; mi++)
#pragma unroll
        for (int ni = 0; ni < 8; ni++) {
            const int col = n0 + wn + ni * 8 + 2 * t;
#pragma unroll
            for (int h = 0; h < 2; h++) {
                const int row = m0 + wm + mi * 16 + g + h * 8;
                __half2 o = __floats2half2_rn(c[mi][ni][2 * h + 0],
                                              c[mi][ni][2 * h + 1]);
                *(uint32_t*)(Cb + (size_t)row * C_DIM + col) = *(uint32_t*)&o;
            }
        }
}

// ---------------------------------------------------------------------------
// D: out[b] = m[b] @ phi_k[b] + bo   (NN, M=256, N=4096, K=256), fp32 out
// grid (32, 4, 16)
// ---------------------------------------------------------------------------
__global__ void __launch_bounds__(128, 4)
out_kernel(const float* __restrict__ bo, float* __restrict__ out)
{
    __shared__ __align__(16) char smem[SMEM_BYTES];
    const int b  = blockIdx.z;
    const int m0 = blockIdx.y * 64;
    const int n0 = blockIdx.x * 128;

    const __half* A = g_m + (size_t)b * C_DIM * C_DIM + (size_t)m0 * C_DIM;
    const __half* B = g_phi_k + (size_t)b * C_DIM * NPIX + n0;

    float c[2][8][4];
    ACC_INIT(c)
    gemm_core<false>(A, B, C_DIM, C_DIM, NPIX, c, smem);

    float* Ob = out + (size_t)b * C_DIM * NPIX;

    EPILOGUE_COORDS
#pragma unroll
    for (int mi = 0; mi < 2; mi++)
#pragma unroll
        for (int ni = 0; ni < 8; ni++) {
            const int col = n0 + wn + ni * 8 + 2 * t;
#pragma unroll
            for (int h = 0; h < 2; h++) {
                const int row = m0 + wm + mi * 16 + g + h * 8;
                const float bi = bo[row];
                float2 o;
                o.x = c[mi][ni][2 * h + 0] + bi;
                o.y = c[mi][ni][2 * h + 1] + bi;
                *(float2*)(Ob + (size_t)row * NPIX + col) = o;
            }
        }
}

// ---------------------------------------------------------------------------
// Launch (guard-safe: no attribute calls, static smem only)
// ---------------------------------------------------------------------------
extern "C" void kernel_launch(void* const* d_in, const int* in_sizes, int n_in,
                              void* d_out, int out_size)
{
    const float* x  = (const float*)d_in[0];
    const float* Wq = (const float*)d_in[1];
    const float* Wk = (const float*)d_in[2];
    const float* Wv = (const float*)d_in[3];
    const float* Wo = (const float*)d_in[4];
    const float* bo = (const float*)d_in[5];
    float* out = (float*)d_out;

    pack_w<<<C_DIM * C_DIM / 256, 256>>>(Wq, Wk, Wv, Wo);
    cvt_x_kernel<<<BATCH * C_DIM * NPIX / 1024, 256>>>(x);

    // A: QKV + phi — grid (32, 12, 16)
    qkv_kernel<<<dim3(NPIX / 128, 768 / 64, BATCH), 128>>>();

    // B: qv split-K partials — grid (2, 4, 64)
    qv_kernel<<<dim3(C_DIM / 128, C_DIM / 64, BATCH * SPLITK), 128>>>();
    qv_reduce<<<BATCH * C_DIM * C_DIM / 256, 256>>>();

    // C: m = Wo @ qv — grid (2, 4, 16)
    wo_qv_kernel<<<dim3(C_DIM / 128, C_DIM / 64, BATCH), 128>>>();

    // D: out = m @ phi_k + bo — grid (32, 4, 16)
    out_kernel<<<dim3(NPIX / 128, C_DIM / 64, BATCH), 128>>>(bo, out);
}